// round 2
// baseline (speedup 1.0000x reference)
#include <cuda_runtime.h>
#include <cuda_bf16.h>
#include <cstdint>
#include <math.h>

// Problem constants
#define BB 8
#define TT 1024
#define EE 768
#define HH 12
#define DD 64
#define MM (BB*TT)        // 8192
#define E3 (3*EE)         // 2304

// Scratch (allocation-free rule: __device__ globals)
__device__ float g_qkv[(size_t)MM * E3];   // 75.5 MB
__device__ float g_attn[(size_t)MM * EE];  // 25 MB

__device__ __forceinline__ uint32_t f2tf(float x) {
    uint32_t r;
    asm("cvt.rna.tf32.f32 %0, %1;" : "=r"(r) : "f"(x));
    return r;
}

__device__ __forceinline__ void mma_tf32(float c[4], const uint32_t a[4],
                                         uint32_t b0, uint32_t b1) {
    asm volatile(
        "mma.sync.aligned.m16n8k8.row.col.f32.tf32.tf32.f32 "
        "{%0,%1,%2,%3}, {%4,%5,%6,%7}, {%8,%9}, {%0,%1,%2,%3};\n"
        : "+f"(c[0]), "+f"(c[1]), "+f"(c[2]), "+f"(c[3])
        : "r"(a[0]), "r"(a[1]), "r"(a[2]), "r"(a[3]), "r"(b0), "r"(b1));
}

// ---------------------------------------------------------------------------
// GEMM: C[M,N] = A[M,K] @ W[K,N] + bias[N]   (all row-major fp32, tf32 mma)
// Block tile 128x128, K-step 32. 256 threads = 8 warps as 2x4 (64x32 each).
// ---------------------------------------------------------------------------
__global__ __launch_bounds__(256) void gemm_bias_kernel(
    const float* __restrict__ A, const float* __restrict__ W,
    const float* __restrict__ bias, float* __restrict__ C,
    int M, int N, int K)
{
    __shared__ uint32_t As[128][36];   // stride 36 ≡ 4 mod 32 -> A-frag conflict-free
    __shared__ uint32_t Ws[32][136];   // stride 136 ≡ 8 mod 32 -> B-frag conflict-free

    const int tid  = threadIdx.x;
    const int m0   = blockIdx.y * 128;
    const int n0   = blockIdx.x * 128;
    const int warp = tid >> 5, lane = tid & 31;
    const int wm   = (warp >> 2) * 64;
    const int wn   = (warp & 3) * 32;
    const int lr   = lane >> 2, lc = lane & 3;

    float acc[4][4][4];
#pragma unroll
    for (int i = 0; i < 4; i++)
#pragma unroll
        for (int j = 0; j < 4; j++)
#pragma unroll
            for (int k = 0; k < 4; k++) acc[i][j][k] = 0.f;

    for (int kk = 0; kk < K; kk += 32) {
        // Load A tile 128x32
#pragma unroll
        for (int i = 0; i < 4; i++) {
            int idx = i * 256 + tid;
            int r = idx >> 3, c = (idx & 7) << 2;
            float4 v = *(const float4*)&A[(size_t)(m0 + r) * K + kk + c];
            As[r][c]     = f2tf(v.x);
            As[r][c + 1] = f2tf(v.y);
            As[r][c + 2] = f2tf(v.z);
            As[r][c + 3] = f2tf(v.w);
        }
        // Load W tile 32x128
#pragma unroll
        for (int i = 0; i < 4; i++) {
            int idx = i * 256 + tid;
            int r = idx >> 5, c = (idx & 31) << 2;
            float4 v = *(const float4*)&W[(size_t)(kk + r) * N + n0 + c];
            Ws[r][c]     = f2tf(v.x);
            Ws[r][c + 1] = f2tf(v.y);
            Ws[r][c + 2] = f2tf(v.z);
            Ws[r][c + 3] = f2tf(v.w);
        }
        __syncthreads();

#pragma unroll
        for (int ks = 0; ks < 4; ks++) {
            const int kb = ks * 8;
            uint32_t a[4][4], b[4][2];
#pragma unroll
            for (int mt = 0; mt < 4; mt++) {
                int mr = wm + mt * 16;
                a[mt][0] = As[mr + lr][kb + lc];
                a[mt][1] = As[mr + lr + 8][kb + lc];
                a[mt][2] = As[mr + lr][kb + lc + 4];
                a[mt][3] = As[mr + lr + 8][kb + lc + 4];
            }
#pragma unroll
            for (int nt = 0; nt < 4; nt++) {
                int nc = wn + nt * 8;
                b[nt][0] = Ws[kb + lc][nc + lr];
                b[nt][1] = Ws[kb + lc + 4][nc + lr];
            }
#pragma unroll
            for (int mt = 0; mt < 4; mt++)
#pragma unroll
                for (int nt = 0; nt < 4; nt++)
                    mma_tf32(acc[mt][nt], a[mt], b[nt][0], b[nt][1]);
        }
        __syncthreads();
    }

    // Epilogue: add bias, store
#pragma unroll
    for (int mt = 0; mt < 4; mt++) {
#pragma unroll
        for (int nt = 0; nt < 4; nt++) {
            int row = m0 + wm + mt * 16 + lr;
            int col = n0 + wn + nt * 8 + 2 * lc;
            float b0 = bias[col], b1 = bias[col + 1];
            C[(size_t)row * N + col]           = acc[mt][nt][0] + b0;
            C[(size_t)row * N + col + 1]       = acc[mt][nt][1] + b1;
            C[(size_t)(row + 8) * N + col]     = acc[mt][nt][2] + b0;
            C[(size_t)(row + 8) * N + col + 1] = acc[mt][nt][3] + b1;
        }
    }
}

// ---------------------------------------------------------------------------
// Flash attention, causal. One block = 64 query rows of one (b,h).
// 4 warps x 16 rows. Bc = 64. tf32 mma for S=QK^T and O+=PV.
// smem: Qs[64][68], Ks[64][68] (aliased as Ps after S), Vs[64][72] = 52 KB dyn
// ---------------------------------------------------------------------------
#define SQ 68
#define SV 72
#define FLASH_SMEM ((2 * 64 * SQ + 64 * SV) * 4)

__global__ __launch_bounds__(128) void flash_attn_kernel(
    const float* __restrict__ qkv, float* __restrict__ attn_out)
{
    extern __shared__ uint32_t sm[];
    uint32_t (*Qs)[SQ] = (uint32_t(*)[SQ])sm;
    uint32_t (*Ks)[SQ] = (uint32_t(*)[SQ])(sm + 64 * SQ);   // also Ps
    uint32_t (*Vs)[SV] = (uint32_t(*)[SV])(sm + 2 * 64 * SQ);

    const int b = blockIdx.z, h = blockIdx.y, qt = blockIdx.x;
    const int tid = threadIdx.x, warp = tid >> 5, lane = tid & 31;
    const int lr = lane >> 2, lc = lane & 3;

    const float* base = qkv + (size_t)b * TT * E3;
    const int qoff = h * DD, koff = EE + h * DD, voff = 2 * EE + h * DD;
    const int qrow0 = qt * 64;

    // Load Q tile (pre-scaled by 1/sqrt(D) = 0.125)
#pragma unroll
    for (int i = 0; i < 8; i++) {
        int idx = i * 128 + tid;
        int r = idx >> 4, c = (idx & 15) << 2;
        float4 v = *(const float4*)&base[(size_t)(qrow0 + r) * E3 + qoff + c];
        Qs[r][c]     = f2tf(v.x * 0.125f);
        Qs[r][c + 1] = f2tf(v.y * 0.125f);
        Qs[r][c + 2] = f2tf(v.z * 0.125f);
        Qs[r][c + 3] = f2tf(v.w * 0.125f);
    }

    float o[8][4];
#pragma unroll
    for (int i = 0; i < 8; i++)
#pragma unroll
        for (int j = 0; j < 4; j++) o[i][j] = 0.f;
    float m0r = -1e30f, m1r = -1e30f, l0 = 0.f, l1 = 0.f;

    for (int kt = 0; kt <= qt; kt++) {
        __syncthreads();  // prev iter done reading Ks(=Ps)/Vs; Q visible (iter 0)
        // Load K,V tiles
#pragma unroll
        for (int i = 0; i < 8; i++) {
            int idx = i * 128 + tid;
            int r = idx >> 4, c = (idx & 15) << 2;
            size_t row = (size_t)(kt * 64 + r) * E3;
            float4 kv = *(const float4*)&base[row + koff + c];
            Ks[r][c]     = f2tf(kv.x);
            Ks[r][c + 1] = f2tf(kv.y);
            Ks[r][c + 2] = f2tf(kv.z);
            Ks[r][c + 3] = f2tf(kv.w);
            float4 vv = *(const float4*)&base[row + voff + c];
            Vs[r][c]     = f2tf(vv.x);
            Vs[r][c + 1] = f2tf(vv.y);
            Vs[r][c + 2] = f2tf(vv.z);
            Vs[r][c + 3] = f2tf(vv.w);
        }
        __syncthreads();

        // S = Q @ K^T (already scaled)
        float s[8][4];
#pragma unroll
        for (int i = 0; i < 8; i++)
#pragma unroll
            for (int j = 0; j < 4; j++) s[i][j] = 0.f;

        uint32_t aq[8][4];
#pragma unroll
        for (int ks = 0; ks < 8; ks++) {
            aq[ks][0] = Qs[warp * 16 + lr][ks * 8 + lc];
            aq[ks][1] = Qs[warp * 16 + lr + 8][ks * 8 + lc];
            aq[ks][2] = Qs[warp * 16 + lr][ks * 8 + lc + 4];
            aq[ks][3] = Qs[warp * 16 + lr + 8][ks * 8 + lc + 4];
        }
#pragma unroll
        for (int nt = 0; nt < 8; nt++) {
#pragma unroll
            for (int ks = 0; ks < 8; ks++) {
                uint32_t b0 = Ks[nt * 8 + lr][ks * 8 + lc];
                uint32_t b1 = Ks[nt * 8 + lr][ks * 8 + lc + 4];
                mma_tf32(s[nt], aq[ks], b0, b1);
            }
        }
        __syncthreads();  // all warps done reading Ks -> safe to reuse as Ps

        // Causal mask (only diagonal tile)
        const int q0 = warp * 16 + lr, q1 = q0 + 8;
        if (kt == qt) {
#pragma unroll
            for (int nt = 0; nt < 8; nt++) {
                int c0 = nt * 8 + 2 * lc;
                if (c0     > q0) s[nt][0] = -1e30f;
                if (c0 + 1 > q0) s[nt][1] = -1e30f;
                if (c0     > q1) s[nt][2] = -1e30f;
                if (c0 + 1 > q1) s[nt][3] = -1e30f;
            }
        }

        // Online softmax
        float t0 = -1e30f, t1 = -1e30f;
#pragma unroll
        for (int nt = 0; nt < 8; nt++) {
            t0 = fmaxf(t0, fmaxf(s[nt][0], s[nt][1]));
            t1 = fmaxf(t1, fmaxf(s[nt][2], s[nt][3]));
        }
        t0 = fmaxf(t0, __shfl_xor_sync(0xffffffff, t0, 1));
        t0 = fmaxf(t0, __shfl_xor_sync(0xffffffff, t0, 2));
        t1 = fmaxf(t1, __shfl_xor_sync(0xffffffff, t1, 1));
        t1 = fmaxf(t1, __shfl_xor_sync(0xffffffff, t1, 2));

        float mn0 = fmaxf(m0r, t0), mn1 = fmaxf(m1r, t1);
        float al0 = __expf(m0r - mn0), al1 = __expf(m1r - mn1);
        m0r = mn0; m1r = mn1;

        float sum0 = 0.f, sum1 = 0.f;
#pragma unroll
        for (int nt = 0; nt < 8; nt++) {
            s[nt][0] = __expf(s[nt][0] - mn0);
            s[nt][1] = __expf(s[nt][1] - mn0);
            s[nt][2] = __expf(s[nt][2] - mn1);
            s[nt][3] = __expf(s[nt][3] - mn1);
            sum0 += s[nt][0] + s[nt][1];
            sum1 += s[nt][2] + s[nt][3];
        }
        sum0 += __shfl_xor_sync(0xffffffff, sum0, 1);
        sum0 += __shfl_xor_sync(0xffffffff, sum0, 2);
        sum1 += __shfl_xor_sync(0xffffffff, sum1, 1);
        sum1 += __shfl_xor_sync(0xffffffff, sum1, 2);
        l0 = l0 * al0 + sum0;
        l1 = l1 * al1 + sum1;

        // Rescale O
#pragma unroll
        for (int nt = 0; nt < 8; nt++) {
            o[nt][0] *= al0; o[nt][1] *= al0;
            o[nt][2] *= al1; o[nt][3] *= al1;
        }

        // Write P (tf32) into Ps (= Ks region); each warp owns its 16 rows
#pragma unroll
        for (int nt = 0; nt < 8; nt++) {
            int c0 = nt * 8 + 2 * lc;
            Ks[warp * 16 + lr][c0]         = f2tf(s[nt][0]);
            Ks[warp * 16 + lr][c0 + 1]     = f2tf(s[nt][1]);
            Ks[warp * 16 + lr + 8][c0]     = f2tf(s[nt][2]);
            Ks[warp * 16 + lr + 8][c0 + 1] = f2tf(s[nt][3]);
        }
        __syncwarp();

        // O += P @ V
#pragma unroll
        for (int ks = 0; ks < 8; ks++) {
            uint32_t ap[4];
            ap[0] = Ks[warp * 16 + lr][ks * 8 + lc];
            ap[1] = Ks[warp * 16 + lr + 8][ks * 8 + lc];
            ap[2] = Ks[warp * 16 + lr][ks * 8 + lc + 4];
            ap[3] = Ks[warp * 16 + lr + 8][ks * 8 + lc + 4];
#pragma unroll
            for (int nt = 0; nt < 8; nt++) {
                uint32_t b0 = Vs[ks * 8 + lc][nt * 8 + lr];
                uint32_t b1 = Vs[ks * 8 + lc + 4][nt * 8 + lr];
                mma_tf32(o[nt], ap, b0, b1);
            }
        }
    }

    // Epilogue: normalize by l, store [B*T, E] at head offset
    const float inv0 = 1.f / l0, inv1 = 1.f / l1;
    const size_t row0 = (size_t)(b * TT + qrow0 + warp * 16 + lr) * EE + h * DD;
#pragma unroll
    for (int nt = 0; nt < 8; nt++) {
        int c = nt * 8 + 2 * lc;
        attn_out[row0 + c]              = o[nt][0] * inv0;
        attn_out[row0 + c + 1]          = o[nt][1] * inv0;
        attn_out[row0 + 8 * EE + c]     = o[nt][2] * inv1;
        attn_out[row0 + 8 * EE + c + 1] = o[nt][3] * inv1;
    }
}

// ---------------------------------------------------------------------------
extern "C" void kernel_launch(void* const* d_in, const int* in_sizes, int n_in,
                              void* d_out, int out_size)
{
    const float* x      = (const float*)d_in[0];
    const float* w_attn = (const float*)d_in[1];
    const float* b_attn = (const float*)d_in[2];
    const float* w_proj = (const float*)d_in[3];
    const float* b_proj = (const float*)d_in[4];
    float* out = (float*)d_out;

    float *qkv_ptr, *attn_ptr;
    cudaGetSymbolAddress((void**)&qkv_ptr, g_qkv);
    cudaGetSymbolAddress((void**)&attn_ptr, g_attn);

    cudaFuncSetAttribute(flash_attn_kernel,
                         cudaFuncAttributeMaxDynamicSharedMemorySize, FLASH_SMEM);

    // 1) QKV = x @ w_attn + b_attn   [8192, 2304]
    gemm_bias_kernel<<<dim3(E3 / 128, MM / 128), 256>>>(
        x, w_attn, b_attn, qkv_ptr, MM, E3, EE);

    // 2) causal flash attention -> g_attn [8192, 768]
    flash_attn_kernel<<<dim3(TT / 64, HH, BB), 128, FLASH_SMEM>>>(qkv_ptr, attn_ptr);

    // 3) out = attn @ w_proj + b_proj [8192, 768]
    gemm_bias_kernel<<<dim3(EE / 128, MM / 128), 256>>>(
        attn_ptr, w_proj, b_proj, out, MM, EE, EE);
}